// round 3
// baseline (speedup 1.0000x reference)
#include <cuda_runtime.h>
#include <stdint.h>

// Problem constants
#define BINSD   512
#define BATCH   64
#define NPTS    4096
#define CELLS   (BATCH * BINSD * BINSD)      // 16,777,216 cells
#define NPOINTS (BATCH * NPTS)               // 262,144 points

#define RES_BLOCKS  256                      // 256*256*4 = 262,144 points
#define FILL_BLOCKS 16384                    // 16384*256*4 = 16,777,216 cells

// Per-cell winner token: 0 = empty, else (n+1) of the winning point in-batch.
// Zero at module load; resolve self-cleans, so each graph replay starts clean.
static __device__ unsigned int g_winner[CELLS];
// Per-cell occupancy bitmap (1 bit per cell, 2 MB). Set by scatter (first point
// per cell), cleared by the fill warps after they consume it.
static __device__ unsigned int g_bitmap[CELLS / 32];

// ---------------------------------------------------------------------------
// Kernel 1: scatter. atomicMax of token into the cell's winner slot; the
// first point to land in a cell (old == 0) sets the cell's bitmap bit.
// ---------------------------------------------------------------------------
__global__ void __launch_bounds__(256) scatter_kernel(
    const float4* __restrict__ pts4) {
    int t0 = (blockIdx.x * 256 + threadIdx.x) * 4;     // first point index
    float4 a = pts4[t0 >> 1];                          // points t0, t0+1
    float4 b = pts4[(t0 >> 1) + 1];                    // points t0+2, t0+3
    int cellbase = (t0 >> 12) << 18;                   // batch never split (4096%4==0)

    float px[4] = {a.x, a.z, b.x, b.z};
    float py[4] = {a.y, a.w, b.y, b.w};
    #pragma unroll
    for (int k = 0; k < 4; k++) {
        // delta = 1/512 exactly: x/delta == x*512.0f bit-exactly; truncation
        // matches astype(int32) for non-negative inputs.
        int row = (int)(px[k] * 512.0f);
        int col = (int)(py[k] * 512.0f);
        int cell = cellbase | (row << 9) | col;
        unsigned int tok = (unsigned int)((t0 + k) & (NPTS - 1)) + 1u;
        unsigned int old = atomicMax(&g_winner[cell], tok);
        if (old == 0u)
            atomicOr(&g_bitmap[cell >> 5], 1u << (cell & 31));
    }
}

// ---------------------------------------------------------------------------
// Kernel 2 (fused): resolve blocks (first, so they launch in wave 0) write the
// winning point into every marked cell and self-clean g_winner. Fill blocks
// write the background ONLY into unmarked cells (bitmap-guided), then clear
// the bitmap word for the next replay. The two roles touch disjoint cells,
// so they overlap freely; resolve hides entirely under the DRAM-bound fill.
// ---------------------------------------------------------------------------
__global__ void __launch_bounds__(256) fused_resolve_fill_kernel(
    float4* __restrict__ out, const float4* __restrict__ pts4) {
    unsigned bid = blockIdx.x;

    if (bid < RES_BLOCKS) {
        // ---- resolve: 4 points per thread ----
        int t0 = (bid * 256 + threadIdx.x) * 4;
        float4 a = pts4[t0 >> 1];
        float4 b = pts4[(t0 >> 1) + 1];
        int cellbase = (t0 >> 12) << 18;

        float px[4] = {a.x, a.z, b.x, b.z};
        float py[4] = {a.y, a.w, b.y, b.w};
        #pragma unroll
        for (int k = 0; k < 4; k++) {
            int row = (int)(px[k] * 512.0f);
            int col = (int)(py[k] * 512.0f);
            int cell = cellbase | (row << 9) | col;
            unsigned int tok = (unsigned int)((t0 + k) & (NPTS - 1)) + 1u;
            // Losers read either the winner's token (!= theirs) or 0 after the
            // winner's reset — both no-ops, so the reset race is safe.
            if (g_winner[cell] == tok) {
                out[cell] = make_float4(1.0f, 1.0f, px[k], py[k]);
                g_winner[cell] = 0u;   // self-clean for next replay
            }
        }
    } else {
        // ---- fill: 4 per-instruction-coalesced float4 stores per thread,
        //      each warp's 32 cells per step map to exactly one bitmap word.
        int fb = bid - RES_BLOCKS;
        int base = fb * 1024 + threadIdx.x;            // float4-element units
        int lane = threadIdx.x & 31;
        const float inv = 1.0f / (float)BINSD;
        #pragma unroll
        for (int k = 0; k < 4; k++) {
            int idx = base + k * 256;
            int word = idx >> 5;                       // bit position == lane
            unsigned int w = 0u;
            if (lane == 0) w = g_bitmap[word];
            w = __shfl_sync(0xffffffffu, w, 0);
            if (!((w >> lane) & 1u)) {
                int j = idx & (BINSD - 1);
                int i = (idx >> 9) & (BINSD - 1);
                __stcs(&out[idx],
                       make_float4(0.63f, 0.63f, (float)j * inv, (float)i * inv));
            }
            if (lane == 0 && w) g_bitmap[word] = 0u;   // self-clean bitmap
        }
    }
}

extern "C" void kernel_launch(void* const* d_in, const int* in_sizes, int n_in,
                              void* d_out, int out_size) {
    const float4* pts4 = (const float4*)d_in[0];  // batch [64, 4096, 2] fp32
    float4* out = (float4*)d_out;                 // [64, 512, 512, 4] fp32

    scatter_kernel<<<NPOINTS / (256 * 4), 256>>>(pts4);
    fused_resolve_fill_kernel<<<RES_BLOCKS + FILL_BLOCKS, 256>>>(out, pts4);
}

// round 4
// speedup vs baseline: 1.2353x; 1.2353x over previous
#include <cuda_runtime.h>
#include <stdint.h>

// Problem constants
#define BINSD   512
#define BATCH   64
#define NPTS    4096
#define CELLS   (BATCH * BINSD * BINSD)      // 16,777,216 cells
#define NPOINTS (BATCH * NPTS)               // 262,144 points

#define RES_BLOCKS  256                      // 256*256*4 = 262,144 points
#define CELLS_PER_WARP 1024                  // 32 bitmap words per warp
#define FILL_BLOCKS (CELLS / (8 * CELLS_PER_WARP))   // 8 warps/block -> 2048

// Per-cell winner token: 0 = empty, else (n+1) of the winning point in-batch.
// Zero at module load; resolve self-cleans -> every graph replay starts clean.
static __device__ unsigned int g_winner[CELLS];
// Per-cell occupancy bitmap (1 bit/cell, 2 MB). Set by scatter on first point
// per cell; cleared by the owning fill warp after consumption.
static __device__ unsigned int g_bitmap[CELLS / 32];

// ---------------------------------------------------------------------------
// Kernel 1: scatter. atomicMax of token into the cell's winner slot; first
// point to land in a cell (old == 0) sets the cell's bitmap bit.
// ---------------------------------------------------------------------------
__global__ void __launch_bounds__(256) scatter_kernel(
    const float4* __restrict__ pts4) {
    int t0 = (blockIdx.x * 256 + threadIdx.x) * 4;     // first point index
    float4 a = pts4[t0 >> 1];                          // points t0, t0+1
    float4 b = pts4[(t0 >> 1) + 1];                    // points t0+2, t0+3
    int cellbase = (t0 >> 12) << 18;                   // batch never split

    float px[4] = {a.x, a.z, b.x, b.z};
    float py[4] = {a.y, a.w, b.y, b.w};
    #pragma unroll
    for (int k = 0; k < 4; k++) {
        // delta = 1/512 exactly: x/delta == x*512.0f bit-exactly; truncation
        // matches astype(int32) for non-negative inputs.
        int row = (int)(px[k] * 512.0f);
        int col = (int)(py[k] * 512.0f);
        int cell = cellbase | (row << 9) | col;
        unsigned int tok = (unsigned int)((t0 + k) & (NPTS - 1)) + 1u;
        unsigned int old = atomicMax(&g_winner[cell], tok);
        if (old == 0u)
            atomicOr(&g_bitmap[cell >> 5], 1u << (cell & 31));
    }
}

// ---------------------------------------------------------------------------
// Kernel 2 (fused): resolve blocks (scheduled first) write the winning point
// into every occupied cell and self-clean g_winner. Fill warps each own 1024
// consecutive cells: ONE coalesced 128B bitmap load (one word per lane) up
// front, then 32 store steps whose skip-mask comes from a register shuffle —
// no memory dependency inside the store loop. Roles touch disjoint cells, so
// resolve hides entirely under the DRAM-bound fill.
// ---------------------------------------------------------------------------
__global__ void __launch_bounds__(256) fused_resolve_fill_kernel(
    float4* __restrict__ out, const float4* __restrict__ pts4) {
    unsigned bid = blockIdx.x;

    if (bid < RES_BLOCKS) {
        // ---- resolve: 4 points per thread, batched loads for MLP ----
        int t0 = (bid * 256 + threadIdx.x) * 4;
        float4 a = pts4[t0 >> 1];
        float4 b = pts4[(t0 >> 1) + 1];
        int cellbase = (t0 >> 12) << 18;

        float px[4] = {a.x, a.z, b.x, b.z};
        float py[4] = {a.y, a.w, b.y, b.w};
        int cell[4];
        unsigned int w[4];
        #pragma unroll
        for (int k = 0; k < 4; k++) {
            int row = (int)(px[k] * 512.0f);
            int col = (int)(py[k] * 512.0f);
            cell[k] = cellbase | (row << 9) | col;
            w[k] = g_winner[cell[k]];                  // 4 loads in flight
        }
        #pragma unroll
        for (int k = 0; k < 4; k++) {
            unsigned int tok = (unsigned int)((t0 + k) & (NPTS - 1)) + 1u;
            // Losers read winner's token (!= theirs) or 0 after the winner's
            // reset — both no-ops, so the reset race is safe.
            if (w[k] == tok) {
                out[cell[k]] = make_float4(1.0f, 1.0f, px[k], py[k]);
                g_winner[cell[k]] = 0u;   // self-clean for next replay
            }
        }
    } else {
        // ---- fill: warp owns 1024 consecutive cells ----
        unsigned fb = bid - RES_BLOCKS;
        int warp = threadIdx.x >> 5;
        int lane = threadIdx.x & 31;
        int wbase = (fb * 8 + warp) * CELLS_PER_WARP;  // first cell of warp

        // One coalesced 128B bitmap read: lane l holds word for cells
        // [wbase + 32*l, wbase + 32*l + 31].
        unsigned int bm = g_bitmap[(wbase >> 5) + lane];

        const float inv = 1.0f / (float)BINSD;
        #pragma unroll
        for (int s = 0; s < 32; s++) {
            unsigned int w = __shfl_sync(0xffffffffu, bm, s);
            int idx = wbase + s * 32 + lane;           // 512B/warp, coalesced
            if (!((w >> lane) & 1u)) {
                int j = idx & (BINSD - 1);
                int i = (idx >> 9) & (BINSD - 1);
                out[idx] = make_float4(0.63f, 0.63f,
                                       (float)j * inv, (float)i * inv);
            }
        }
        if (bm) g_bitmap[(wbase >> 5) + lane] = 0u;    // rare self-clean
    }
}

extern "C" void kernel_launch(void* const* d_in, const int* in_sizes, int n_in,
                              void* d_out, int out_size) {
    const float4* pts4 = (const float4*)d_in[0];  // batch [64, 4096, 2] fp32
    float4* out = (float4*)d_out;                 // [64, 512, 512, 4] fp32

    scatter_kernel<<<NPOINTS / (256 * 4), 256>>>(pts4);
    fused_resolve_fill_kernel<<<RES_BLOCKS + FILL_BLOCKS, 256>>>(out, pts4);
}

// round 6
// speedup vs baseline: 1.2797x; 1.0359x over previous
#include <cuda_runtime.h>
#include <stdint.h>

// Problem constants
#define BINSD   512
#define BATCH   64
#define NPTS    4096
#define CELLS   (BATCH * BINSD * BINSD)      // 16,777,216 cells
#define NPOINTS (BATCH * NPTS)               // 262,144 points

#define RES_BLOCKS  256                      // 256*256*4 = 262,144 points
#define FILL_BLOCKS 2048                     // 2048 blk * 8 warps * 1024 cells

// Per-cell winner token: 0 = empty, else (n+1) of the winning point in-batch.
// Zero at module load; resolve self-cleans -> every graph replay starts clean.
static __device__ unsigned int g_winner[CELLS];
// TRANSPOSED per-cell occupancy bitmap (1 bit/cell, 2 MB):
//   for cell c: word = (c>>10)*32 + (c&31), bit = (c>>5)&31.
// Fill-thread (warp-slice W, lane l) loads word W*32+l once and owns the bits
// for exactly its 32 cells {W*1024 + s*32 + l} — no shuffles, no reloads.
static __device__ unsigned int g_bitmap[CELLS / 32];

// ---------------------------------------------------------------------------
// Kernel 1: scatter. Returnless atomics only (RED, fire-and-forget):
// atomicMax token into the winner slot, unconditional atomicOr into the
// transposed bitmap (duplicates are idempotent).
// ---------------------------------------------------------------------------
__global__ void __launch_bounds__(256) scatter_kernel(
    const float2* __restrict__ pts) {
    int t = blockIdx.x * 256 + threadIdx.x;            // 0 .. NPOINTS-1
    float2 p = pts[t];
    // delta = 1/512 exactly: x/delta == x*512.0f bit-exactly; truncation
    // matches astype(int32) for non-negative inputs.
    int row = (int)(p.x * 512.0f);
    int col = (int)(p.y * 512.0f);
    int cell = ((t >> 12) << 18) | (row << 9) | col;
    unsigned int tok = (unsigned int)(t & (NPTS - 1)) + 1u;
    atomicMax(&g_winner[cell], tok);                           // RED (no return)
    atomicOr(&g_bitmap[((cell >> 10) << 5) | (cell & 31)],     // RED (no return)
             1u << ((cell >> 5) & 31));
}

// ---------------------------------------------------------------------------
// Kernel 2 (fused): resolve blocks (scheduled first) write winning points into
// occupied cells; fill warps write background into the complementary cells.
// Disjoint cell sets -> resolve hides fully under the DRAM-bound fill.
// ---------------------------------------------------------------------------
__global__ void __launch_bounds__(256) fused_resolve_fill_kernel(
    float4* __restrict__ out, const float4* __restrict__ pts4) {
    unsigned bid = blockIdx.x;

    if (bid < RES_BLOCKS) {
        // ---- resolve: 4 points per thread, loads batched for MLP ----
        int t0 = (bid * 256 + threadIdx.x) * 4;
        float4 a = pts4[t0 >> 1];
        float4 b = pts4[(t0 >> 1) + 1];
        int cellbase = (t0 >> 12) << 18;               // batch never split

        float px[4] = {a.x, a.z, b.x, b.z};
        float py[4] = {a.y, a.w, b.y, b.w};
        int cell[4];
        unsigned int w[4];
        #pragma unroll
        for (int k = 0; k < 4; k++) {
            int row = (int)(px[k] * 512.0f);
            int col = (int)(py[k] * 512.0f);
            cell[k] = cellbase | (row << 9) | col;
            w[k] = g_winner[cell[k]];                  // 4 loads in flight
        }
        #pragma unroll
        for (int k = 0; k < 4; k++) {
            unsigned int tok = (unsigned int)((t0 + k) & (NPTS - 1)) + 1u;
            // Losers read winner's token (!= theirs) or 0 after the winner's
            // reset — both no-ops, so the reset race is safe.
            if (w[k] == tok) {
                out[cell[k]] = make_float4(1.0f, 1.0f, px[k], py[k]);
                g_winner[cell[k]] = 0u;                // self-clean
            }
        }
    } else {
        // ---- fill: warp owns 1024 consecutive cells; thread owns 32 cells
        //      {wbase + s*32 + lane}. One coalesced 4B bitmap load per thread
        //      gives its whole skip mask — the store loop has NO memory or
        //      cross-lane dependency.
        unsigned fb = bid - RES_BLOCKS;
        int warp = threadIdx.x >> 5;
        int lane = threadIdx.x & 31;
        unsigned W = fb * 8 + warp;                    // warp-slice number
        int wbase = (int)(W << 10);                    // first cell of slice

        unsigned int m = g_bitmap[(W << 5) + lane];    // own 32-cell mask

        // idx = wbase + s*32 + lane, wbase multiple of 1024:
        //   z = (idx & 511)/512 = lane/512 + (s&15)/16
        //   w = ((idx>>9) & 511)/512 : wf0 for s<16, wf0 + 1/512 for s>=16
        const float inv = 1.0f / (float)BINSD;
        float zf0 = (float)lane * inv;
        float wf0 = (float)((wbase >> 9) & (BINSD - 1)) * inv;
        float wf1 = wf0 + inv;

        #pragma unroll
        for (int s = 0; s < 16; s++) {
            if (!((m >> s) & 1u)) {
                out[wbase + s * 32 + lane] = make_float4(
                    0.63f, 0.63f, zf0 + (float)s * (1.0f / 16.0f), wf0);
            }
        }
        #pragma unroll
        for (int s = 16; s < 32; s++) {
            if (!((m >> s) & 1u)) {
                out[wbase + s * 32 + lane] = make_float4(
                    0.63f, 0.63f, zf0 + (float)(s - 16) * (1.0f / 16.0f), wf1);
            }
        }
        if (m) g_bitmap[(W << 5) + lane] = 0u;         // rare self-clean
    }
}

extern "C" void kernel_launch(void* const* d_in, const int* in_sizes, int n_in,
                              void* d_out, int out_size) {
    const float2* pts = (const float2*)d_in[0];   // batch [64, 4096, 2] fp32
    float4* out = (float4*)d_out;                 // [64, 512, 512, 4] fp32

    scatter_kernel<<<NPOINTS / 256, 256>>>(pts);
    fused_resolve_fill_kernel<<<RES_BLOCKS + FILL_BLOCKS, 256>>>(
        out, (const float4*)pts);
}

// round 8
// speedup vs baseline: 1.6848x; 1.3166x over previous
#include <cuda_runtime.h>
#include <stdint.h>

// Problem constants
#define BINSD   512
#define BATCH   64
#define NPTS    4096
#define CELLS   (BATCH * BINSD * BINSD)      // 16,777,216 cells
#define NPOINTS (BATCH * NPTS)               // 262,144 points

#define SCAT_BLOCKS 1024                     // 1024*256 = 262,144 points, 1/thread
#define FILL_BLOCKS 65536                    // 65536*256 = 16,777,216 cells, 1/thread

// Per-cell winner token: 0 = empty, else (n+1) of the winning point in-batch.
// Zero at module load; resolve self-cleans -> every graph replay starts clean.
static __device__ unsigned int g_winner[CELLS];

// ---------------------------------------------------------------------------
// Kernel 1 (fused): scatter blocks first (wave 0, hidden under the fill),
// then the R1-shaped fill: ONE float4 store per thread, huge grid. This is
// the empirically fastest store shape on this chip (67% DRAM in R1); batched
// multi-store loops measured ~45% in R2/R4/R6.
// ---------------------------------------------------------------------------
__global__ void __launch_bounds__(256) fused_scatter_fill_kernel(
    float4* __restrict__ out, const float2* __restrict__ pts) {
    unsigned bid = blockIdx.x;

    if (bid >= SCAT_BLOCKS) {
        // ---- fill: one float4 per thread ----
        int idx = (bid - SCAT_BLOCKS) * 256 + threadIdx.x;   // 0 .. CELLS-1
        const float inv = 1.0f / (float)BINSD;
        int j = idx & (BINSD - 1);
        int i = (idx >> 9) & (BINSD - 1);
        out[idx] = make_float4(0.63f, 0.63f, (float)j * inv, (float)i * inv);
    } else {
        // ---- scatter: one point per thread, returnless atomic (RED) ----
        int t = bid * 256 + threadIdx.x;                     // 0 .. NPOINTS-1
        float2 p = pts[t];
        // delta = 1/512 exactly: x/delta == x*512.0f bit-exactly; truncation
        // matches astype(int32) for non-negative inputs.
        int row = (int)(p.x * 512.0f);
        int col = (int)(p.y * 512.0f);
        int cell = ((t >> 12) << 18) | (row << 9) | col;
        unsigned int tok = (unsigned int)(t & (NPTS - 1)) + 1u;
        atomicMax(&g_winner[cell], tok);                     // no return -> RED
    }
}

// ---------------------------------------------------------------------------
// Kernel 2: resolve. 4 points per thread; all 4 random winner loads issued
// before any consumption (4x MLP vs the 1-load chain that ran at issue=3.9%).
// The winning point overwrites its cell and resets the token. Losers read
// either the winner's token (!= theirs) or 0 after the reset - both no-ops.
// ---------------------------------------------------------------------------
__global__ void __launch_bounds__(256) resolve_kernel(
    float4* __restrict__ out, const float4* __restrict__ pts4) {
    int t0 = (blockIdx.x * 256 + threadIdx.x) * 4;           // first point
    float4 a = pts4[t0 >> 1];                                // points t0,t0+1
    float4 b = pts4[(t0 >> 1) + 1];                          // points t0+2,t0+3
    int cellbase = (t0 >> 12) << 18;                         // batch never split

    float px[4] = {a.x, a.z, b.x, b.z};
    float py[4] = {a.y, a.w, b.y, b.w};
    int cell[4];
    unsigned int w[4];
    #pragma unroll
    for (int k = 0; k < 4; k++) {
        int row = (int)(px[k] * 512.0f);
        int col = (int)(py[k] * 512.0f);
        cell[k] = cellbase | (row << 9) | col;
        w[k] = g_winner[cell[k]];                            // 4 loads in flight
    }
    #pragma unroll
    for (int k = 0; k < 4; k++) {
        unsigned int tok = (unsigned int)((t0 + k) & (NPTS - 1)) + 1u;
        if (w[k] == tok) {
            out[cell[k]] = make_float4(1.0f, 1.0f, px[k], py[k]);
            g_winner[cell[k]] = 0u;                          // self-clean
        }
    }
}

extern "C" void kernel_launch(void* const* d_in, const int* in_sizes, int n_in,
                              void* d_out, int out_size) {
    const float2* pts = (const float2*)d_in[0];   // batch [64, 4096, 2] fp32
    float4* out = (float4*)d_out;                 // [64, 512, 512, 4] fp32

    fused_scatter_fill_kernel<<<SCAT_BLOCKS + FILL_BLOCKS, 256>>>(out, pts);
    resolve_kernel<<<NPOINTS / (256 * 4), 256>>>(out, (const float4*)pts);
}